// round 10
// baseline (speedup 1.0000x reference)
#include <cuda_runtime.h>
#include <math.h>

// ---------------------------------------------------------------------------
// L=32, M=63, SL=2016, nlm=1024, B=32, C=64, H=8, D=8
// Separable SHT (validated R7/R8, rel_err 7e-7):
//   Ypinv[k, t*63+p] = D[k,t] e^{-i m_k phi_p},  D = Re(Ypinv) at p=0
//   Ymat [t*63+p, k] = C[t,k] e^{+i m_k phi_p},  C = Re(Ymat)  at p=0
// Complex I/O = real part only (astype semantics).
// ---------------------------------------------------------------------------
#define SL    2016
#define NPHI  63
#define NLM   1024
#define NR    2048
#define NKR   512
#define NK3   1536
#define NKO   4096
#define NOUT  (32 * 64 * SL)

__device__ float  g_D [32 * NLM];      // forward Legendre D[t][k]
__device__ float  g_C [32 * NLM];      // inverse Legendre C[t][k]
__device__ float  g_Ef[64 * 64];       // twiddles [n=2m+c][p]; p=63 col zero
__device__ float  g_fc [NR * NLM];     // gathered f at idx positions
__device__ float2 g_kqkv[NK3 * NLM];   // spectral q|k|v kernels [row][k]
__device__ float2 g_koc [NKO * NLM];   // spectral output kernel [row][k]
__device__ float2 g_kot [NLM * NKO];   // transposed [k][row]
__device__ float2 g_G  [NR * NLM];     // FQ * conj(FK)   [r][k]
__device__ float2 g_FV [NR * NLM];     // FV              [r][k]
__device__ float2 g_P  [NR * NLM];     // FV * FA         [r][k]
__device__ float2 g_fot[NLM * NR];     // transposed [k][r]

__device__ __forceinline__ int iclamp(int i, int n) {
    return (i < 0) ? 0 : ((i >= n) ? n - 1 : i);
}
__device__ __forceinline__ int isqrt_dev(int k) {
    int l = (int)sqrtf((float)k);
    while ((l + 1) * (l + 1) <= k) ++l;
    while (l * l > k) --l;
    return l;
}

// ---------------------------------------------------------------------------
__global__ void build_tables(const float* __restrict__ Ym, const float* __restrict__ Yp) {
    int i = blockIdx.x * 256 + threadIdx.x;
    if (i < 32 * NLM) {
        int t = i >> 10, k = i & 1023;
        g_D[i] = Yp[(size_t)k * SL + t * NPHI];
        g_C[i] = Ym[(size_t)t * NPHI * NLM + k];
    }
    if (i < 64 * 64) {
        int n = i >> 6, p = i & 63;
        float v = 0.f;
        if (p < NPHI) {
            int m = n >> 1;
            int q = (m * p) % NPHI;
            float ang = 6.283185307179586f * (float)q / (float)NPHI;
            v = (n & 1) ? -sinf(ang) : cosf(ang);
        }
        g_Ef[i] = v;
    }
}

__global__ void gather_fc(const float* __restrict__ f_in, int nf,
                          const int* __restrict__ idx, int ni) {
    int i = blockIdx.x * blockDim.x + threadIdx.x;
    if (i >= NR * NLM) return;
    int r = i >> 10, k = i & (NLM - 1);
    int s = idx[iclamp(k, ni)];
    s = iclamp(s, SL);
    g_fc[i] = f_in[iclamp(r * SL + s, nf)];
}

// ---------------------------------------------------------------------------
// Forward SHT of weights, 2 rows per block (table reads amortized).
// ---------------------------------------------------------------------------
__global__ __launch_bounds__(256) void wfwd(const float* __restrict__ kq,
                                            const float* __restrict__ kk,
                                            const float* __restrict__ kv,
                                            const float* __restrict__ ko) {
    const int r0 = blockIdx.x * 2;
    __shared__ float Ef[64][65];
    __shared__ float X [32][64];
    __shared__ float Z [2][32][65];
    const int tid = threadIdx.x;

    for (int i = tid; i < 64 * 64; i += 256) Ef[i >> 6][i & 63] = g_Ef[i];

    for (int q = 0; q < 2; ++q) {
        int r = r0 + q;
        const float* src; int row;
        if (r < 512)       { src = kq; row = r; }
        else if (r < 1024) { src = kk; row = r - 512; }
        else if (r < 1536) { src = kv; row = r - 1024; }
        else               { src = ko; row = r - 1536; }
        __syncthreads();
        for (int i = tid; i < 32 * 63; i += 256) {
            int t = i / 63, p = i - t * 63;
            X[t][p] = src[(size_t)row * SL + i];
        }
        __syncthreads();
        // Z[t][c] = sum_p X[t][p] * Ef[c][p]  (2x4 tiles over 256 threads)
        {
            const int tg = tid >> 4, cg = tid & 15;
            float acc[2][4];
#pragma unroll
            for (int i = 0; i < 2; ++i)
#pragma unroll
                for (int j = 0; j < 4; ++j) acc[i][j] = 0.f;
#pragma unroll 7
            for (int p = 0; p < 63; ++p) {
                float x0 = X[tg * 2][p], x1 = X[tg * 2 + 1][p];
                float ev[4];
#pragma unroll
                for (int j = 0; j < 4; ++j) ev[j] = Ef[cg * 4 + j][p];
#pragma unroll
                for (int j = 0; j < 4; ++j) {
                    acc[0][j] += x0 * ev[j];
                    acc[1][j] += x1 * ev[j];
                }
            }
#pragma unroll
            for (int i = 0; i < 2; ++i)
#pragma unroll
                for (int j = 0; j < 4; ++j) Z[q][tg * 2 + i][cg * 4 + j] = acc[i][j];
        }
    }
    __syncthreads();

    // Legendre for both rows, sharing each g_D load
    for (int k = tid; k < NLM; k += 256) {
        int l = isqrt_dev(k);
        int m = k - l * l - l;
        int am = (m < 0) ? -m : m;
        float re0 = 0.f, im0 = 0.f, re1 = 0.f, im1 = 0.f;
#pragma unroll 8
        for (int t = 0; t < 32; ++t) {
            float dd = g_D[t * NLM + k];
            re0 += dd * Z[0][t][2 * am];
            im0 += dd * Z[0][t][2 * am + 1];
            re1 += dd * Z[1][t][2 * am];
            im1 += dd * Z[1][t][2 * am + 1];
        }
        if (m < 0) { im0 = -im0; im1 = -im1; }
        int r = r0;
        if (r < NK3) g_kqkv[(size_t)r * NLM + k] = make_float2(re0, im0);
        else         g_koc[(size_t)(r - NK3) * NLM + k] = make_float2(re0, im0);
        r = r0 + 1;
        if (r < NK3) g_kqkv[(size_t)r * NLM + k] = make_float2(re1, im1);
        else         g_koc[(size_t)(r - NK3) * NLM + k] = make_float2(re1, im1);
    }
}

// ---------------------------------------------------------------------------
// Head-mix as batched GEMM: block = (k16, h). Weights read ONCE from DRAM.
//  G[r][k] = FQ*conj(FK), FV[r][k];  r = b*64 + h*8 + d
// ---------------------------------------------------------------------------
__global__ __launch_bounds__(256) void qkv_gemm() {
    __shared__ float  F  [16][257];     // [j][b*8+c]
    __shared__ float2 Wsh[3][16][65];   // [mat][j][c*8+d]
    const int h = blockIdx.y;
    const int k0 = blockIdx.x * 16;
    const int tid = threadIdx.x;

    for (int i = tid; i < 256 * 16; i += 256) {
        int rr = i >> 4, j = i & 15;
        int b = rr >> 3, c = rr & 7;
        F[j][rr] = g_fc[(size_t)((b << 6) + (h << 3) + c) * NLM + k0 + j];
    }
    for (int i = tid; i < 3 * 64 * 16; i += 256) {
        int mat = i >> 10;
        int rr = (i >> 4) & 63;
        int j = i & 15;
        Wsh[mat][j][rr] = g_kqkv[(size_t)(mat * NKR + h * 64 + rr) * NLM + k0 + j];
    }
    __syncthreads();

    const int b = tid >> 3, d = tid & 7;
    const int r = (b << 6) + (h << 3) + d;
#pragma unroll 4
    for (int j = 0; j < 16; ++j) {
        float qr = 0, qi = 0, kr = 0, ki = 0, vr = 0, vi = 0;
#pragma unroll
        for (int c = 0; c < 8; ++c) {
            float f = F[j][b * 8 + c];
            float2 wq = Wsh[0][j][c * 8 + d];
            float2 wk = Wsh[1][j][c * 8 + d];
            float2 wv = Wsh[2][j][c * 8 + d];
            qr += f * wq.x; qi += f * wq.y;
            kr += f * wk.x; ki += f * wk.y;
            vr += f * wv.x; vi += f * wv.y;
        }
        g_G [(size_t)r * NLM + k0 + j] = make_float2(qr * kr + qi * ki, qi * kr - qr * ki);
        g_FV[(size_t)r * NLM + k0 + j] = make_float2(vr, vi);
    }
}

// ---------------------------------------------------------------------------
// MEGA (2 rows per block): G -> folded inverse Legendre -> inverse phi-DFT ->
// softmax -> forward phi-DFT -> forward Legendre -> P = FV*FA
// ---------------------------------------------------------------------------
__global__ __launch_bounds__(256) void mega() {
    __shared__ float  Ef[64][65];
    __shared__ float2 Gb[1024];        // G; reused as A[32][64] floats
    __shared__ float  U [32][65];
    __shared__ float  red[32];
    const int tid = threadIdx.x;

    for (int i = tid; i < 64 * 64; i += 256) Ef[i >> 6][i & 63] = g_Ef[i];

    for (int rowi = 0; rowi < 2; ++rowi) {
        const int r = blockIdx.x * 2 + rowi;
        __syncthreads();
        for (int i = tid; i < 1024; i += 256) Gb[i] = g_G[(size_t)r * NLM + i];
        __syncthreads();

        // folded inverse Legendre
        for (int it = tid; it < 1024; it += 256) {
            int t = it >> 5, m = it & 31;
            float ur, ui;
            if (m == 0) {
                float re = 0.f;
                for (int l = 0; l < 32; ++l) {
                    int k = l * l + l;
                    re += g_C[t * NLM + k] * Gb[k].x;
                }
                ur = re; ui = 0.f;
            } else {
                float rp = 0.f, ip = 0.f, rm = 0.f, im2 = 0.f;
                for (int l = m; l < 32; ++l) {
                    int kb = l * l + l;
                    float cp = g_C[t * NLM + kb + m];
                    float cm = g_C[t * NLM + kb - m];
                    float2 gp = Gb[kb + m];
                    float2 gm = Gb[kb - m];
                    rp += cp * gp.x; ip += cp * gp.y;
                    rm += cm * gm.x; im2 += cm * gm.y;
                }
                ur = rp + rm; ui = ip - im2;
            }
            U[t][2 * m]     = ur;
            U[t][2 * m + 1] = ui;
        }
        __syncthreads();

        // inverse phi-DFT
        float* A = reinterpret_cast<float*>(Gb);
        {
            const int tg = tid >> 4, pg = tid & 15;
            float acc[2][4];
#pragma unroll
            for (int i = 0; i < 2; ++i)
#pragma unroll
                for (int j = 0; j < 4; ++j) acc[i][j] = 0.f;
#pragma unroll 8
            for (int c = 0; c < 64; ++c) {
                float u0 = U[tg * 2][c], u1 = U[tg * 2 + 1][c];
                float ev[4];
#pragma unroll
                for (int j = 0; j < 4; ++j) ev[j] = Ef[c][pg * 4 + j];
#pragma unroll
                for (int j = 0; j < 4; ++j) {
                    acc[0][j] += u0 * ev[j];
                    acc[1][j] += u1 * ev[j];
                }
            }
#pragma unroll
            for (int i = 0; i < 2; ++i)
#pragma unroll
                for (int j = 0; j < 4; ++j) A[(tg * 2 + i) * 64 + pg * 4 + j] = acc[i][j];
        }
        __syncthreads();
        if (tid < 32) A[tid * 64 + 63] = -1e30f;
        __syncthreads();

        // softmax over 2016 (pad -> exp 0)
        {
            float m = -1e30f;
            for (int i = tid; i < 2048; i += 256) m = fmaxf(m, A[i]);
#pragma unroll
            for (int o = 16; o; o >>= 1) m = fmaxf(m, __shfl_xor_sync(0xffffffffu, m, o));
            if ((tid & 31) == 0) red[tid >> 5] = m;
            __syncthreads();
            if (tid < 32) {
                float v = (tid < 8) ? red[tid] : -1e30f;
#pragma unroll
                for (int o = 4; o; o >>= 1) v = fmaxf(v, __shfl_xor_sync(0xffffffffu, v, o));
                if (tid == 0) red[0] = v;
            }
            __syncthreads();
            m = red[0];
            __syncthreads();
            float s = 0.f;
            for (int i = tid; i < 2048; i += 256) {
                float e = expf(A[i] - m);
                A[i] = e;
                s += e;
            }
#pragma unroll
            for (int o = 16; o; o >>= 1) s += __shfl_xor_sync(0xffffffffu, s, o);
            if ((tid & 31) == 0) red[tid >> 5] = s;
            __syncthreads();
            if (tid < 32) {
                float v = (tid < 8) ? red[tid] : 0.f;
#pragma unroll
                for (int o = 4; o; o >>= 1) v += __shfl_xor_sync(0xffffffffu, v, o);
                if (tid == 0) red[0] = v;
            }
            __syncthreads();
            float inv = 1.0f / red[0];
            for (int i = tid; i < 2048; i += 256) A[i] *= inv;
        }
        __syncthreads();

        // forward phi-DFT (A -> U)
        {
            const int tg = tid >> 4, cg = tid & 15;
            float acc[2][4];
#pragma unroll
            for (int i = 0; i < 2; ++i)
#pragma unroll
                for (int j = 0; j < 4; ++j) acc[i][j] = 0.f;
#pragma unroll 7
            for (int p = 0; p < 63; ++p) {
                float a0 = A[(tg * 2) * 64 + p], a1 = A[(tg * 2 + 1) * 64 + p];
                float ev[4];
#pragma unroll
                for (int j = 0; j < 4; ++j) ev[j] = Ef[cg * 4 + j][p];
#pragma unroll
                for (int j = 0; j < 4; ++j) {
                    acc[0][j] += a0 * ev[j];
                    acc[1][j] += a1 * ev[j];
                }
            }
#pragma unroll
            for (int i = 0; i < 2; ++i)
#pragma unroll
                for (int j = 0; j < 4; ++j) U[tg * 2 + i][cg * 4 + j] = acc[i][j];
        }
        __syncthreads();

        // forward Legendre + FV*FA
#pragma unroll
        for (int i = 0; i < 4; ++i) {
            int k = tid + i * 256;
            int l = isqrt_dev(k);
            int m = k - l * l - l;
            int am = (m < 0) ? -m : m;
            float re = 0.f, im = 0.f;
#pragma unroll 8
            for (int t = 0; t < 32; ++t) {
                float dd = g_D[t * NLM + k];
                re += dd * U[t][2 * am];
                im += dd * U[t][2 * am + 1];
            }
            if (m < 0) im = -im;
            float2 fv = g_FV[(size_t)r * NLM + k];
            g_P[(size_t)r * NLM + k] =
                make_float2(fv.x * re - fv.y * im, fv.x * im + fv.y * re);
        }
    }
}

// ---------------------------------------------------------------------------
__global__ void transpose_gen(int sel) {
    const float2* in = sel ? g_P : g_koc;
    float2* out = sel ? g_fot : g_kot;
    const int R = sel ? NR : NKO;
    __shared__ __align__(16) float2 tile[32][33];
    int c0 = blockIdx.x * 32, r0 = blockIdx.y * 32;
#pragma unroll
    for (int j = 0; j < 4; ++j) {
        int r = r0 + threadIdx.y + j * 8;
        tile[threadIdx.y + j * 8][threadIdx.x] = in[(size_t)r * NLM + c0 + threadIdx.x];
    }
    __syncthreads();
#pragma unroll
    for (int j = 0; j < 4; ++j) {
        int c = c0 + threadIdx.y + j * 8;
        out[(size_t)c * R + r0 + threadIdx.x] = tile[threadIdx.x][threadIdx.y + j * 8];
    }
}

__global__ void zero_out_f(float* out, int n) {
    int i = blockIdx.x * blockDim.x + threadIdx.x;
    if (i < n) out[i] = 0.f;
}

__global__ __launch_bounds__(256) void out_scatter(const int* __restrict__ idx, int ni,
                                                   float* __restrict__ out) {
    __shared__ __align__(16) float2 Fsh[64 * 33];
    int k = blockIdx.x;
    for (int j = threadIdx.x; j < NR; j += 256) {
        float2 v = g_fot[(size_t)k * NR + j];
        int bb = j >> 6, cc = j & 63;
        Fsh[cc * 33 + bb] = v;
    }
    __syncthreads();
    int w = threadIdx.x >> 5;
    int b = threadIdx.x & 31;
    const float2* W = g_kot + (size_t)k * NKO;
    float re[8];
#pragma unroll
    for (int i = 0; i < 8; ++i) re[i] = 0.f;
#pragma unroll 4
    for (int c = 0; c < 64; ++c) {
        float2 F = Fsh[c * 33 + b];
#pragma unroll
        for (int i = 0; i < 8; ++i) {
            float2 ww = W[(w + i * 8) * 64 + c];
            re[i] += F.x * ww.x - F.y * ww.y;
        }
    }
    int s = idx[iclamp(k, ni)];
    s = iclamp(s, SL);
#pragma unroll
    for (int i = 0; i < 8; ++i) {
        int o = w + i * 8;
        out[(size_t)((b << 6) + o) * SL + s] = re[i];
    }
}

// ---------------------------------------------------------------------------
extern "C" void kernel_launch(void* const* d_in, const int* in_sizes, int n_in,
                              void* d_out, int out_size) {
    const float* f_in = (const float*)d_in[0];
    const float* kq   = (const float*)d_in[1];
    const float* kk   = (const float*)d_in[2];
    const float* kv   = (const float*)d_in[3];
    const float* ko   = (const float*)d_in[4];
    const float* Ym   = (const float*)d_in[5];
    const float* Yp   = (const float*)d_in[6];
    const int*   idx  = (const int*)d_in[7];
    float* out = (float*)d_out;

    build_tables<<<128, 256>>>(Ym, Yp);
    gather_fc<<<(NR * NLM) / 256, 256>>>(f_in, in_sizes[0], idx, in_sizes[7]);

    wfwd<<<2816, 256>>>(kq, kk, kv, ko);                 // 5632 rows / 2
    transpose_gen<<<dim3(32, 128), dim3(32, 8)>>>(0);    // koc -> kot

    qkv_gemm<<<dim3(64, 8), 256>>>();                    // G, FV
    mega<<<1024, 256>>>();                               // 2048 rows / 2
    transpose_gen<<<dim3(32, 64), dim3(32, 8)>>>(1);     // P -> fot

    zero_out_f<<<(NOUT + 255) / 256, 256>>>(out, NOUT);
    out_scatter<<<NLM, 256>>>(idx, in_sizes[7], out);
}

// round 11
// speedup vs baseline: 1.0605x; 1.0605x over previous
#include <cuda_runtime.h>
#include <math.h>

// ---------------------------------------------------------------------------
// L=32, M=63, SL=2016, nlm=1024, B=32, C=64, H=8, D=8
// Separable SHT (validated R7-R10, rel_err ~7e-7):
//   Ypinv[k, t*63+p] = D[k,t] e^{-i m_k phi_p},  D = Re(Ypinv) at p=0
//   Ymat [t*63+p, k] = C[t,k] e^{+i m_k phi_p},  C = Re(Ymat)  at p=0
// Complex I/O = real part only (astype semantics).
// ---------------------------------------------------------------------------
#define SL    2016
#define NPHI  63
#define NLM   1024
#define NR    2048
#define NKR   512
#define NK3   1536
#define NKO   4096
#define NOUT  (32 * 64 * SL)

__device__ float  g_D [32 * NLM];      // forward Legendre D[t][k]
__device__ float  g_C [32 * NLM];      // inverse Legendre C[t][k]
__device__ float  g_Ef[64 * 64];       // twiddles [n=2m+c][p]; p=63 zero
__device__ int    g_sidx[NLM];         // k -> spatial s (from real idx array)
__device__ int    g_kinv[SL];          // s -> k or -1
__device__ float2 g_kqkv[NK3 * NLM];   // spectral q|k|v kernels [row][k]
__device__ float2 g_koc [NKO * NLM];   // spectral output kernel [row][k]
__device__ float2 g_kot [NLM * NKO];   // transposed [k][row]
__device__ float2 g_P   [NR * NLM];    // FV * FA [r][k]
__device__ float2 g_fot [NLM * NR];    // transposed [k][r]
__device__ float  g_OS  [(size_t)NLM * NR];   // out stage [k][j]
__device__ float  g_OST [(size_t)NR * NLM];   // out stage [j][k]

__device__ __forceinline__ int iclamp(int i, int n) {
    return (i < 0) ? 0 : ((i >= n) ? n - 1 : i);
}
__device__ __forceinline__ int isqrt_dev(int k) {
    int l = (int)sqrtf((float)k);
    while ((l + 1) * (l + 1) <= k) ++l;
    while (l * l > k) --l;
    return l;
}

// ---------------------------------------------------------------------------
__global__ void build_tables(const float* __restrict__ Ym, const float* __restrict__ Yp,
                             const int* __restrict__ idx, int ni) {
    int i = blockIdx.x * 256 + threadIdx.x;
    if (i < 32 * NLM) {
        int t = i >> 10, k = i & 1023;
        g_D[i] = Yp[(size_t)k * SL + t * NPHI];
        g_C[i] = Ym[(size_t)t * NPHI * NLM + k];
    }
    if (i < 64 * 64) {
        int n = i >> 6, p = i & 63;
        float v = 0.f;
        if (p < NPHI) {
            int m = n >> 1;
            int q = (m * p) % NPHI;
            float ang = 6.283185307179586f * (float)q / (float)NPHI;
            v = (n & 1) ? -sinf(ang) : cosf(ang);
        }
        g_Ef[i] = v;
    }
    if (i < NLM) g_sidx[i] = iclamp(idx[iclamp(i, ni)], SL);
    if (i < SL)  g_kinv[i] = -1;
}

__global__ void build_inv() {
    int k = blockIdx.x * 256 + threadIdx.x;
    if (k < NLM) g_kinv[g_sidx[k]] = k;
}

// ---------------------------------------------------------------------------
// Forward SHT of weights: one block per row (5632), 128 threads.
// phi-DFT with float4 smem ops + Legendre.
// ---------------------------------------------------------------------------
__global__ __launch_bounds__(128) void wfwd(const float* __restrict__ kq,
                                            const float* __restrict__ kk,
                                            const float* __restrict__ kv,
                                            const float* __restrict__ ko) {
    int r = blockIdx.x;
    const float* src; int row; float2* out; int outr;
    if (r < 512)       { src = kq; row = r;        out = g_kqkv; outr = r; }
    else if (r < 1024) { src = kk; row = r - 512;  out = g_kqkv; outr = r; }
    else if (r < 1536) { src = kv; row = r - 1024; out = g_kqkv; outr = r; }
    else               { src = ko; row = r - 1536; out = g_koc;  outr = r - 1536; }

    __shared__ __align__(16) float Ef[64][68];
    __shared__ __align__(16) float X [32][64];
    __shared__ __align__(16) float Z [32][68];
    const int tid = threadIdx.x;

    for (int i = tid; i < 64 * 68; i += 128) {
        int c = i / 68, p = i - c * 68;
        Ef[c][p] = (p < 63) ? g_Ef[c * 64 + p] : 0.f;
    }
    for (int i = tid; i < 32 * 63; i += 128) {
        int t = i / 63, p = i - t * 63;
        X[t][p] = src[(size_t)row * SL + i];
    }
    if (tid < 32) X[tid][63] = 0.f;
    __syncthreads();

    // Z[t][c] = sum_p X[t][p] * Ef[c][p]   (4x4 tiles, p unrolled by 4)
    {
        const int tg = tid >> 4;           // 8 groups, t0 = tg*4
        const int cg = tid & 15;           // c0 = cg*4
        float acc[4][4];
#pragma unroll
        for (int i = 0; i < 4; ++i)
#pragma unroll
            for (int j = 0; j < 4; ++j) acc[i][j] = 0.f;
#pragma unroll
        for (int p0 = 0; p0 < 64; p0 += 4) {
            float4 xv[4], ev[4];
#pragma unroll
            for (int i = 0; i < 4; ++i)
                xv[i] = *reinterpret_cast<const float4*>(&X[tg * 4 + i][p0]);
#pragma unroll
            for (int j = 0; j < 4; ++j)
                ev[j] = *reinterpret_cast<const float4*>(&Ef[cg * 4 + j][p0]);
#pragma unroll
            for (int i = 0; i < 4; ++i)
#pragma unroll
                for (int j = 0; j < 4; ++j)
                    acc[i][j] += xv[i].x * ev[j].x + xv[i].y * ev[j].y
                               + xv[i].z * ev[j].z + xv[i].w * ev[j].w;
        }
#pragma unroll
        for (int i = 0; i < 4; ++i) {
            float4 v = make_float4(acc[i][0], acc[i][1], acc[i][2], acc[i][3]);
            *reinterpret_cast<float4*>(&Z[tg * 4 + i][cg * 4]) = v;
        }
    }
    __syncthreads();

    // Legendre: out[k] = sum_t D[t][k] * Z[t][2am(,+1)]
    for (int k = tid; k < NLM; k += 128) {
        int l = isqrt_dev(k);
        int m = k - l * l - l;
        int am = (m < 0) ? -m : m;
        float re = 0.f, im = 0.f;
#pragma unroll 8
        for (int t = 0; t < 32; ++t) {
            float dd = g_D[t * NLM + k];
            float2 u = *reinterpret_cast<const float2*>(&Z[t][2 * am]);
            re += dd * u.x;
            im += dd * u.y;
        }
        if (m < 0) im = -im;
        out[(size_t)outr * NLM + k] = make_float2(re, im);
    }
}

// ---------------------------------------------------------------------------
// MEGA: per attention-row r (2048 blocks): qkv mix (weights L2-resident) ->
// folded inverse Legendre -> inverse phi-DFT -> softmax -> forward phi-DFT ->
// forward Legendre -> P = FV*FA
// ---------------------------------------------------------------------------
__global__ __launch_bounds__(256) void mega(const float* __restrict__ f_in) {
    const int r = blockIdx.x;
    const int b = r >> 6, ch = r & 63, h = ch >> 3, d = ch & 7;

    __shared__ __align__(16) float  Ef[64][68];
    __shared__ __align__(16) float2 Gb[1024];     // G; reused as A[32][64] floats
    __shared__ __align__(16) float  U [32][68];
    __shared__ float red[8];
    const int tid = threadIdx.x;

    for (int i = tid; i < 64 * 68; i += 256) {
        int c = i / 68, p = i - c * 68;
        Ef[c][p] = (p < 63) ? g_Ef[c * 64 + p] : 0.f;
    }

    // ---- qkv head mixing: G to smem, FV to registers ----------------------
    float2 fv[4];
#pragma unroll
    for (int i = 0; i < 4; ++i) {
        int k = tid + i * 256;
        int s = g_sidx[k];
        float qr = 0, qi = 0, kr = 0, ki = 0, vr = 0, vi = 0;
#pragma unroll
        for (int c = 0; c < 8; ++c) {
            float f = f_in[(size_t)((b << 6) + (h << 3) + c) * SL + s];
            int row = ((h << 3) + c) * 8 + d;
            float2 wq = g_kqkv[(size_t)row * NLM + k];
            float2 wk = g_kqkv[(size_t)(row + NKR) * NLM + k];
            float2 wv = g_kqkv[(size_t)(row + 2 * NKR) * NLM + k];
            qr += f * wq.x; qi += f * wq.y;
            kr += f * wk.x; ki += f * wk.y;
            vr += f * wv.x; vi += f * wv.y;
        }
        Gb[k] = make_float2(qr * kr + qi * ki, qi * kr - qr * ki);
        fv[i] = make_float2(vr, vi);
    }
    __syncthreads();

    // ---- folded inverse Legendre ------------------------------------------
    for (int it = tid; it < 1024; it += 256) {
        int t = it >> 5, m = it & 31;
        float ur, ui;
        if (m == 0) {
            float re = 0.f;
            for (int l = 0; l < 32; ++l) {
                int k = l * l + l;
                re += g_C[t * NLM + k] * Gb[k].x;
            }
            ur = re; ui = 0.f;
        } else {
            float rp = 0.f, ip = 0.f, rm = 0.f, im2 = 0.f;
            for (int l = m; l < 32; ++l) {
                int kb = l * l + l;
                float cp = g_C[t * NLM + kb + m];
                float cm = g_C[t * NLM + kb - m];
                float2 gp = Gb[kb + m];
                float2 gm = Gb[kb - m];
                rp += cp * gp.x; ip += cp * gp.y;
                rm += cm * gm.x; im2 += cm * gm.y;
            }
            ur = rp + rm; ui = ip - im2;
        }
        *reinterpret_cast<float2*>(&U[t][2 * m]) = make_float2(ur, ui);
    }
    __syncthreads();

    // ---- inverse phi-DFT: A[t][p] = sum_c U[t][c] * Ef[c][p] --------------
    float* A = reinterpret_cast<float*>(Gb);   // [t*64 + p]
    {
        const int tg = tid >> 4;               // t0 = tg*2
        const int pg = tid & 15;               // p0 = pg*4
        float acc[2][4];
#pragma unroll
        for (int i = 0; i < 2; ++i)
#pragma unroll
            for (int j = 0; j < 4; ++j) acc[i][j] = 0.f;
#pragma unroll 8
        for (int c = 0; c < 64; ++c) {
            float u0 = U[tg * 2][c], u1 = U[tg * 2 + 1][c];
            float4 ev = *reinterpret_cast<const float4*>(&Ef[c][pg * 4]);
            acc[0][0] += u0 * ev.x; acc[0][1] += u0 * ev.y;
            acc[0][2] += u0 * ev.z; acc[0][3] += u0 * ev.w;
            acc[1][0] += u1 * ev.x; acc[1][1] += u1 * ev.y;
            acc[1][2] += u1 * ev.z; acc[1][3] += u1 * ev.w;
        }
#pragma unroll
        for (int i = 0; i < 2; ++i) {
            float4 v = make_float4(acc[i][0], acc[i][1], acc[i][2], acc[i][3]);
            *reinterpret_cast<float4*>(&A[(tg * 2 + i) * 64 + pg * 4]) = v;
        }
    }
    __syncthreads();
    if (tid < 32) A[tid * 64 + 63] = -1e30f;   // pad col excluded from softmax
    __syncthreads();

    // ---- softmax over 2016 (pad -> exp 0) ---------------------------------
    {
        float m = -1e30f;
        for (int i = tid; i < 2048; i += 256) m = fmaxf(m, A[i]);
#pragma unroll
        for (int o = 16; o; o >>= 1) m = fmaxf(m, __shfl_xor_sync(0xffffffffu, m, o));
        if ((tid & 31) == 0) red[tid >> 5] = m;
        __syncthreads();
        if (tid < 32) {
            float v = (tid < 8) ? red[tid] : -1e30f;
#pragma unroll
            for (int o = 4; o; o >>= 1) v = fmaxf(v, __shfl_xor_sync(0xffffffffu, v, o));
            if (tid == 0) red[0] = v;
        }
        __syncthreads();
        m = red[0];
        __syncthreads();
        float s = 0.f;
        for (int i = tid; i < 2048; i += 256) {
            float e = expf(A[i] - m);
            A[i] = e;
            s += e;
        }
#pragma unroll
        for (int o = 16; o; o >>= 1) s += __shfl_xor_sync(0xffffffffu, s, o);
        if ((tid & 31) == 0) red[tid >> 5] = s;
        __syncthreads();
        if (tid < 32) {
            float v = (tid < 8) ? red[tid] : 0.f;
#pragma unroll
            for (int o = 4; o; o >>= 1) v += __shfl_xor_sync(0xffffffffu, v, o);
            if (tid == 0) red[0] = v;
        }
        __syncthreads();
        float inv = 1.0f / red[0];
        for (int i = tid; i < 2048; i += 256) A[i] *= inv;
    }
    __syncthreads();

    // ---- forward phi-DFT: U[t][c] = sum_p A[t][p] * Ef[c][p] --------------
    {
        const int tg = tid >> 4;               // t0 = tg*2
        const int cg = tid & 15;               // c0 = cg*4
        float acc[2][4];
#pragma unroll
        for (int i = 0; i < 2; ++i)
#pragma unroll
            for (int j = 0; j < 4; ++j) acc[i][j] = 0.f;
#pragma unroll
        for (int p0 = 0; p0 < 64; p0 += 4) {
            float4 a0 = *reinterpret_cast<const float4*>(&A[(tg * 2) * 64 + p0]);
            float4 a1 = *reinterpret_cast<const float4*>(&A[(tg * 2 + 1) * 64 + p0]);
            float4 ev[4];
#pragma unroll
            for (int j = 0; j < 4; ++j)
                ev[j] = *reinterpret_cast<const float4*>(&Ef[cg * 4 + j][p0]);
#pragma unroll
            for (int j = 0; j < 4; ++j) {
                acc[0][j] += a0.x * ev[j].x + a0.y * ev[j].y + a0.z * ev[j].z + a0.w * ev[j].w;
                acc[1][j] += a1.x * ev[j].x + a1.y * ev[j].y + a1.z * ev[j].z + a1.w * ev[j].w;
            }
        }
#pragma unroll
        for (int i = 0; i < 2; ++i) {
            float4 v = make_float4(acc[i][0], acc[i][1], acc[i][2], acc[i][3]);
            *reinterpret_cast<float4*>(&U[tg * 2 + i][cg * 4]) = v;
        }
    }
    __syncthreads();

    // ---- forward Legendre + FV*FA -----------------------------------------
#pragma unroll
    for (int i = 0; i < 4; ++i) {
        int k = tid + i * 256;
        int l = isqrt_dev(k);
        int m = k - l * l - l;
        int am = (m < 0) ? -m : m;
        float re = 0.f, im = 0.f;
#pragma unroll 8
        for (int t = 0; t < 32; ++t) {
            float dd = g_D[t * NLM + k];
            float2 u = *reinterpret_cast<const float2*>(&U[t][2 * am]);
            re += dd * u.x;
            im += dd * u.y;
        }
        if (m < 0) im = -im;
        g_P[(size_t)r * NLM + k] =
            make_float2(fv[i].x * re - fv[i].y * im, fv[i].x * im + fv[i].y * re);
    }
}

// ---------------------------------------------------------------------------
// Complex transpose: sel=0: g_koc[4096][1024]->g_kot; sel=1: g_P[2048][1024]->g_fot
// ---------------------------------------------------------------------------
__global__ void transpose_gen(int sel) {
    const float2* in = sel ? g_P : g_koc;
    float2* out = sel ? g_fot : g_kot;
    const int R = sel ? NR : NKO;
    __shared__ __align__(16) float2 tile[32][33];
    int c0 = blockIdx.x * 32, r0 = blockIdx.y * 32;
#pragma unroll
    for (int j = 0; j < 4; ++j) {
        int r = r0 + threadIdx.y + j * 8;
        tile[threadIdx.y + j * 8][threadIdx.x] = in[(size_t)r * NLM + c0 + threadIdx.x];
    }
    __syncthreads();
#pragma unroll
    for (int j = 0; j < 4; ++j) {
        int c = c0 + threadIdx.y + j * 8;
        out[(size_t)c * R + r0 + threadIdx.x] = tile[threadIdx.x][threadIdx.y + j * 8];
    }
}

// ---------------------------------------------------------------------------
// Final projection per k: stage[k][j] = Re( sum_c F[b,c] * W[o,c] ), j=b*64+o.
// Coalesced stage writes via smem re-layout.
// ---------------------------------------------------------------------------
__global__ __launch_bounds__(256) void out_gemm() {
    __shared__ __align__(16) float2 Fsh[64 * 33];   // [c][b]
    __shared__ float Osh[64][33];                   // [o][b]
    int k = blockIdx.x;
    for (int j = threadIdx.x; j < NR; j += 256) {
        float2 v = g_fot[(size_t)k * NR + j];
        int bb = j >> 6, cc = j & 63;
        Fsh[cc * 33 + bb] = v;
    }
    __syncthreads();
    int w = threadIdx.x >> 5;
    int b = threadIdx.x & 31;
    const float2* W = g_kot + (size_t)k * NKO;
    float re[8];
#pragma unroll
    for (int i = 0; i < 8; ++i) re[i] = 0.f;
#pragma unroll 4
    for (int c = 0; c < 64; ++c) {
        float2 F = Fsh[c * 33 + b];
#pragma unroll
        for (int i = 0; i < 8; ++i) {
            float2 ww = W[(w + i * 8) * 64 + c];
            re[i] += F.x * ww.x - F.y * ww.y;
        }
    }
#pragma unroll
    for (int i = 0; i < 8; ++i) Osh[w + i * 8][b] = re[i];
    __syncthreads();
    float* st = g_OS + (size_t)k * NR;
    for (int j = threadIdx.x; j < NR; j += 256)
        st[j] = Osh[j & 63][j >> 6];
}

// Float transpose g_OS[1024][2048] -> g_OST[2048][1024]
__global__ void transpose_f() {
    __shared__ float tile[32][33];
    int j0 = blockIdx.x * 32, k0 = blockIdx.y * 32;
#pragma unroll
    for (int jj = 0; jj < 4; ++jj) {
        int k = k0 + threadIdx.y + jj * 8;
        tile[threadIdx.y + jj * 8][threadIdx.x] = g_OS[(size_t)k * NR + j0 + threadIdx.x];
    }
    __syncthreads();
#pragma unroll
    for (int jj = 0; jj < 4; ++jj) {
        int j = j0 + threadIdx.y + jj * 8;
        g_OST[(size_t)j * NLM + k0 + threadIdx.x] = tile[threadIdx.x][threadIdx.y + jj * 8];
    }
}

// Coalesced row write: out[j][s] = (kinv[s] >= 0) ? stage[j][kinv[s]] : 0
__global__ __launch_bounds__(256) void row_write(float* __restrict__ out) {
    int j = blockIdx.x;
    const float* st = g_OST + (size_t)j * NLM;
    float* row = out + (size_t)j * SL;
    for (int s = threadIdx.x; s < SL; s += 256) {
        int kv = g_kinv[s];
        row[s] = (kv >= 0) ? st[kv] : 0.f;
    }
}

// ---------------------------------------------------------------------------
extern "C" void kernel_launch(void* const* d_in, const int* in_sizes, int n_in,
                              void* d_out, int out_size) {
    const float* f_in = (const float*)d_in[0];
    const float* kq   = (const float*)d_in[1];
    const float* kk   = (const float*)d_in[2];
    const float* kv   = (const float*)d_in[3];
    const float* ko   = (const float*)d_in[4];
    const float* Ym   = (const float*)d_in[5];
    const float* Yp   = (const float*)d_in[6];
    const int*   idx  = (const int*)d_in[7];
    float* out = (float*)d_out;

    build_tables<<<128, 256>>>(Ym, Yp, idx, in_sizes[7]);
    build_inv<<<4, 256>>>();

    wfwd<<<5632, 128>>>(kq, kk, kv, ko);
    transpose_gen<<<dim3(32, 128), dim3(32, 8)>>>(0);   // koc -> kot

    mega<<<NR, 256>>>(f_in);
    transpose_gen<<<dim3(32, 64), dim3(32, 8)>>>(1);    // P -> fot

    out_gemm<<<NLM, 256>>>();
    transpose_f<<<dim3(64, 32), dim3(32, 8)>>>();
    row_write<<<NR, 256>>>(out);
}